// round 16
// baseline (speedup 1.0000x reference)
#include <cuda_runtime.h>
#include <cuda_bf16.h>
#include <math.h>
#include <stdint.h>

// Problem constants
#define B_  8
#define T_  1024
#define D_  512
#define H_  8
#define DK_ 64
#define BT_ 8192      // B*T
#define BH_ 64        // B*H

// single dynamic-smem symbol (gemm + attention)
extern __shared__ char dsmem[];

// ---------------- scratch (device globals; no allocation allowed) ----------------
__device__ float g_proj[6][BT_ * D_];        // 0:qm 1:qc 2:km 3:kc 4:vm 5:vc
__device__ __nv_bfloat16 g_chi[2][BT_ * D_];
__device__ __nv_bfloat16 g_clo[2][BT_ * D_];
// attention operands (bf16 hi/lo)
__device__ unsigned short g_qh[BH_ * T_ * 128];   // [bh][t][dcat] K-major
__device__ unsigned short g_ql[BH_ * T_ * 128];
__device__ unsigned short g_kh[BH_ * T_ * 128];
__device__ unsigned short g_kl[BH_ * T_ * 128];
__device__ unsigned short g_vmh[BH_ * DK_ * T_]; // [bh][d][s] (V transposed)
__device__ unsigned short g_vml[BH_ * DK_ * T_];
__device__ unsigned short g_vch[BH_ * DK_ * T_];
__device__ unsigned short g_vcl[BH_ * DK_ * T_];
__device__ float g_bq[BH_ * T_];
__device__ float g_bk[BH_ * T_];

// ================= fast transcendentals on FMA/ALU pipes =================
__device__ __forceinline__ float fexp(float x)
{
    x = fmaxf(x, -80.0f);
    float t = x * 1.4426950408889634f;            // log2(e)
    float nf = t + 12582912.0f;                   // 1.5*2^23 round-to-nearest
    int   ei = __float_as_int(nf) - 0x4b400000;
    float n  = nf - 12582912.0f;
    float f  = t - n;                             // f in [-0.5, 0.5]
    float p  = 1.3338464e-3f;
    p = fmaf(p, f, 9.6180203e-3f);
    p = fmaf(p, f, 5.5503614e-2f);
    p = fmaf(p, f, 2.4022647e-1f);
    p = fmaf(p, f, 6.9314718e-1f);
    p = fmaf(p, f, 1.0f);
    return __int_as_float(__float_as_int(p) + (ei << 23));
}
__device__ __forceinline__ float fsqrt(float z)
{
    z = fmaxf(z, 1e-30f);
    float r = __int_as_float(0x5f3759df - (__float_as_int(z) >> 1));
    r = r * fmaf(-0.5f * z * r, r, 1.5f);
    r = r * fmaf(-0.5f * z * r, r, 1.5f);
    return z * r;
}

// ================= mma.sync / cp.async helpers =================
__device__ __forceinline__ uint32_t smem_u32(const void* p) {
    uint32_t a;
    asm("{ .reg .u64 t; cvta.to.shared.u64 t, %1; cvt.u32.u64 %0, t; }" : "=r"(a) : "l"(p));
    return a;
}
__device__ __forceinline__ void ldsm_x4(uint32_t* r, uint32_t addr) {
    asm volatile("ldmatrix.sync.aligned.m8n8.x4.shared.b16 {%0,%1,%2,%3}, [%4];"
                 : "=r"(r[0]), "=r"(r[1]), "=r"(r[2]), "=r"(r[3]) : "r"(addr));
}
__device__ __forceinline__ void ldsm_x2(uint32_t* r, uint32_t addr) {
    asm volatile("ldmatrix.sync.aligned.m8n8.x2.shared.b16 {%0,%1}, [%2];"
                 : "=r"(r[0]), "=r"(r[1]) : "r"(addr));
}
__device__ __forceinline__ void mma16816(float* c, const uint32_t* a, const uint32_t* b) {
    asm volatile("mma.sync.aligned.m16n8k16.row.col.f32.bf16.bf16.f32 "
                 "{%0,%1,%2,%3}, {%4,%5,%6,%7}, {%8,%9}, {%0,%1,%2,%3};"
                 : "+f"(c[0]), "+f"(c[1]), "+f"(c[2]), "+f"(c[3])
                 : "r"(a[0]), "r"(a[1]), "r"(a[2]), "r"(a[3]), "r"(b[0]), "r"(b[1]));
}
__device__ __forceinline__ void cp16(uint32_t saddr, const void* gptr) {
    asm volatile("cp.async.ca.shared.global [%0], [%1], 16;" :: "r"(saddr), "l"(gptr));
}
#define CP_COMMIT() asm volatile("cp.async.commit_group;" ::: "memory")
#define CP_WAIT0()  asm volatile("cp.async.wait_group 0;" ::: "memory")
// swizzle for [R][64]-bf16 tiles (128B rows) — gemm BK=64
__device__ __forceinline__ uint32_t swzK(uint32_t r, uint32_t g) {
    return r * 128u + ((g ^ (r & 7u)) << 4);
}
// swizzle for [R][128]-bf16 tiles (256B rows) — attn
__device__ __forceinline__ uint32_t swz128(uint32_t r, uint32_t g) {
    return r * 256u + ((g ^ (r & 7u)) << 4);
}
__device__ __forceinline__ void bf16split(float x, unsigned short& h, unsigned short& l) {
    __nv_bfloat16 hb = __float2bfloat16(x);
    __nv_bfloat16 lb = __float2bfloat16(x - __bfloat162float(hb));
    h = __bfloat16_as_ushort(hb);
    l = __bfloat16_as_ushort(lb);
}
// split 8 consecutive fp32 into hi/lo uint4 pair
__device__ __forceinline__ void split8(const float* src, uint4& hi, uint4& lo)
{
    float4 a0 = *(const float4*)src;
    float4 a1 = *(const float4*)(src + 4);
    float x[8] = {a0.x, a0.y, a0.z, a0.w, a1.x, a1.y, a1.z, a1.w};
    unsigned short hh[8], ll[8];
#pragma unroll
    for (int i = 0; i < 8; i++) bf16split(x[i], hh[i], ll[i]);
    hi = *(uint4*)hh;
    lo = *(uint4*)ll;
}
// online softmax merge: (m,s) += (cm, cs)
__device__ __forceinline__ void osm_merge(float& m, float& s, float cm, float cs)
{
    float nm = fmaxf(m, cm);
    s = s * fexp(m - nm) + cs * fexp(cm - nm);
    m = nm;
}

// ================= bf16x3 GEMM via mma.sync, BK=64, fused input split =================
#define GEMM_SMEM 65536
struct GemmArgs { const float* bias[6]; const float* Af[6]; const float* Wf[6]; float* out; int is_out; };

__global__ void __launch_bounds__(256, 2) gemm_mma(GemmArgs ga)
{
    char* smem = dsmem;

    const int z = blockIdx.z;
    const int n0 = blockIdx.x * 128;
    const int m0 = blockIdx.y * 128;
    const int tid = threadIdx.x;
    const int lane = tid & 31;
    const int w = tid >> 5;
    const int wm = w >> 2;
    const int wn = w & 3;

    const __nv_bfloat16 *Ah = nullptr, *Al = nullptr;
    const float *Af = nullptr, *Wf;
    const float* bias;
    float* C;
    if (ga.is_out) {
        Ah = g_chi[z]; Al = g_clo[z];
        Wf = ga.Wf[4 + z];
        bias = ga.bias[4 + z];
        C = ga.out + (size_t)z * BT_ * D_;
    } else {
        int ws = (z < 4) ? (z & 1) : (z - 2);
        Af = ga.Af[z];
        Wf = ga.Wf[ws];
        bias = ga.bias[ws];
        C = &g_proj[z][0];
    }

    const uint32_t sb = smem_u32(smem);
    const uint32_t bAhi = sb, bAlo = sb + 16384, bWhi = sb + 32768, bWlo = sb + 49152;
    char* pAhi = smem;
    char* pAlo = smem + 16384;
    char* pWhi = smem + 32768;
    char* pWlo = smem + 49152;

    float acc[4][4][4];
#pragma unroll
    for (int i = 0; i < 4; i++)
#pragma unroll
        for (int j = 0; j < 4; j++)
#pragma unroll
            for (int q = 0; q < 4; q++) acc[i][j][q] = 0.f;

    const int a_r = lane & 15, a_c = lane >> 4;
    const int b_r = (lane & 7) + ((lane >> 4) << 3);
    const int b_c = (lane >> 3) & 1;

    for (int kt = 0; kt < 512; kt += 64) {
        __syncthreads();
#pragma unroll
        for (int i = 0; i < 4; i++) {
            int idx = i * 256 + tid;
            uint32_t r = (uint32_t)(idx >> 3), g = (uint32_t)(idx & 7);
            uint32_t so = swzK(r, g);
            size_t goA = (size_t)(m0 + r) * 512 + kt + g * 8;
            size_t goW = (size_t)(n0 + r) * 512 + kt + g * 8;
            uint4 hi, lo;
            split8(Wf + goW, hi, lo);
            *(uint4*)(pWhi + so) = hi;
            *(uint4*)(pWlo + so) = lo;
            if (ga.is_out) {
                cp16(bAhi + so, Ah + goA);
                cp16(bAlo + so, Al + goA);
            } else {
                split8(Af + goA, hi, lo);
                *(uint4*)(pAhi + so) = hi;
                *(uint4*)(pAlo + so) = lo;
            }
        }
        if (ga.is_out) { CP_COMMIT(); CP_WAIT0(); }
        __syncthreads();

#pragma unroll
        for (int ks = 0; ks < 4; ks++) {
            uint32_t bhi[4][2], blo[4][2];
#pragma unroll
            for (int pr = 0; pr < 2; pr++) {
                uint32_t r = (uint32_t)(wn * 32 + pr * 16 + b_r);
                uint32_t cb = (uint32_t)(ks * 2 + b_c);
                uint32_t t[4];
                ldsm_x4(t, bWhi + swzK(r, cb));
                bhi[2 * pr][0] = t[0]; bhi[2 * pr][1] = t[1];
                bhi[2 * pr + 1][0] = t[2]; bhi[2 * pr + 1][1] = t[3];
                ldsm_x4(t, bWlo + swzK(r, cb));
                blo[2 * pr][0] = t[0]; blo[2 * pr][1] = t[1];
                blo[2 * pr + 1][0] = t[2]; blo[2 * pr + 1][1] = t[3];
            }
            uint32_t a[4][4];
            {
                uint32_t cb = (uint32_t)(ks * 2 + a_c);
#pragma unroll
                for (int mt = 0; mt < 4; mt++) {
                    uint32_t r = (uint32_t)(wm * 64 + mt * 16 + a_r);
                    ldsm_x4(a[mt], bAhi + swzK(r, cb));
                }
            }
#pragma unroll
            for (int mt = 0; mt < 4; mt++)
#pragma unroll
                for (int nt = 0; nt < 4; nt++) {
                    mma16816(acc[mt][nt], a[mt], bhi[nt]);
                    mma16816(acc[mt][nt], a[mt], blo[nt]);
                }
            {
                uint32_t cb = (uint32_t)(ks * 2 + a_c);
#pragma unroll
                for (int mt = 0; mt < 4; mt++) {
                    uint32_t r = (uint32_t)(wm * 64 + mt * 16 + a_r);
                    ldsm_x4(a[mt], bAlo + swzK(r, cb));
                }
            }
#pragma unroll
            for (int mt = 0; mt < 4; mt++)
#pragma unroll
                for (int nt = 0; nt < 4; nt++)
                    mma16816(acc[mt][nt], a[mt], bhi[nt]);
        }
    }

    const int g8 = lane >> 2;
    const int t2 = lane & 3;
#pragma unroll
    for (int nt = 0; nt < 4; nt++) {
        int col = n0 + wn * 32 + nt * 8 + 2 * t2;
        float2 b2 = *(const float2*)(bias + col);
#pragma unroll
        for (int mt = 0; mt < 4; mt++) {
            int row0 = m0 + wm * 64 + mt * 16 + g8;
            float2 v0 = make_float2(acc[mt][nt][0] + b2.x, acc[mt][nt][1] + b2.y);
            float2 v1 = make_float2(acc[mt][nt][2] + b2.x, acc[mt][nt][3] + b2.y);
            *(float2*)(C + (size_t)row0 * 512 + col) = v0;
            *(float2*)(C + (size_t)(row0 + 8) * 512 + col) = v1;
        }
    }
}

// ---------------- merged pack kernel (unchanged) ----------------
__global__ void pack_all()
{
    __shared__ float tile[32][65];
    int tid = threadIdx.x;

    if (blockIdx.x < 4096) {
        int idx = blockIdx.x * 256 + tid;
        int g = idx & 15;
        int t = (idx >> 4) & 1023;
        int bh = idx >> 14;
        int b = bh >> 3, h = bh & 7;
        size_t base = (size_t)(b * 1024 + t) * 512 + h * 64;

        float qv[8], kv[8];
        float bq_part = 0.f, bk_part = 0.f;
        if (g < 8) {
#pragma unroll
            for (int j = 0; j < 8; j++) {
                qv[j] = g_proj[0][base + g * 8 + j];
                kv[j] = g_proj[2][base + g * 8 + j];
                bq_part += qv[j] * qv[j];
                bk_part += kv[j] * kv[j];
            }
        } else {
#pragma unroll
            for (int j = 0; j < 8; j++) {
                float qr = g_proj[1][base + (g - 8) * 8 + j];
                float kr = g_proj[3][base + (g - 8) * 8 + j];
                bq_part += qr;
                bk_part += kr;
                qv[j] = fsqrt(fmaxf(qr, 1e-24f));
                kv[j] = fsqrt(fmaxf(kr, 1e-24f));
            }
        }
#pragma unroll
        for (int o = 8; o; o >>= 1) {
            bq_part += __shfl_xor_sync(0xffffffffu, bq_part, o);
            bk_part += __shfl_xor_sync(0xffffffffu, bk_part, o);
        }
        if (g == 0) {
            g_bq[bh * T_ + t] = bq_part;
            g_bk[bh * T_ + t] = bk_part;
        }

        unsigned short qh8[8], ql8[8], kh8[8], kl8[8];
#pragma unroll
        for (int j = 0; j < 8; j++) {
            bf16split(qv[j], qh8[j], ql8[j]);
            bf16split(kv[j], kh8[j], kl8[j]);
        }
        size_t o = ((size_t)(bh * 1024 + t)) * 128 + g * 8;
        *(uint4*)(g_qh + o) = *(uint4*)qh8;
        *(uint4*)(g_ql + o) = *(uint4*)ql8;
        *(uint4*)(g_kh + o) = *(uint4*)kh8;
        *(uint4*)(g_kl + o) = *(uint4*)kl8;
    } else {
        int bx = blockIdx.x - 4096;
        int s0 = (bx & 31) * 32;
        int z = (bx >> 5) & 1;
        int bh = bx >> 6;
        int b = bh >> 3, h = bh & 7;
        const float* src = g_proj[4 + z];

#pragma unroll
        for (int e = 0; e < 8; e++) {
            int idx = e * 256 + tid;
            int sl = idx >> 6, d = idx & 63;
            tile[sl][d] = src[(size_t)(b * 1024 + s0 + sl) * 512 + h * 64 + d];
        }
        __syncthreads();
        unsigned short* dh = z ? g_vch : g_vmh;
        unsigned short* dl = z ? g_vcl : g_vml;
#pragma unroll
        for (int e = 0; e < 8; e++) {
            int idx = e * 256 + tid;
            int d = idx >> 5, sl = idx & 31;
            unsigned short hh, ll;
            bf16split(tile[sl][d], hh, ll);
            size_t o = ((size_t)(bh * 64 + d)) * 1024 + s0 + sl;
            dh[o] = hh;
            dl[o] = ll;
        }
    }
}

// ---------------- fused attention: TR=32, 512 threads, cp.async staging ----------------
#define TR 32
#define SC_STRIDE 1028
#define STG_OFF (32 * SC_STRIDE * 4)          // 131584
#define ATTN_SMEM (STG_OFF + 98304)           // 229888

__device__ __forceinline__ float wredmax(float v)
{
#pragma unroll
    for (int o = 16; o; o >>= 1) v = fmaxf(v, __shfl_xor_sync(0xffffffffu, v, o));
    return v;
}
__device__ __forceinline__ float wredsum(float v)
{
#pragma unroll
    for (int o = 16; o; o >>= 1) v += __shfl_xor_sync(0xffffffffu, v, o);
    return v;
}

__global__ void __launch_bounds__(512, 1) attn_kernel(const float* __restrict__ gammas)
{
    char* smem = dsmem;
    float* sc = (float*)smem;
    char* stg = smem + STG_OFF;

    const int bh = blockIdx.y;
    const int tile = (int)gridDim.x - 1 - (int)blockIdx.x;
    const int t0 = tile * TR;
    const int tid = threadIdx.x;
    const int lane = tid & 31, w = tid >> 5;
    const int NT = (t0 + TR + 127) / 128;
    const int b = bh >> 3, h = bh & 7;

    const int a_r = lane & 15, a_c = lane >> 4;
    const int b_r = (lane & 7) + ((lane >> 4) << 3);
    const int b_c = (lane >> 3) & 1;
    const int g8 = lane >> 2, t2 = lane & 3;

    // staging addresses
    const uint32_t sb = smem_u32(stg);
    const uint32_t aQh = sb, aQl = sb + 8192, aKh = sb + 16384, aKl = sb + 49152;
    const uint32_t aPh = sb, aPl = sb + 8192, aP2h = sb + 16384, aP2l = sb + 24576;
    const uint32_t aVmh = sb + 32768, aVml = sb + 49152, aVch = sb + 65536, aVcl = sb + 81920;
    float2* part = (float2*)stg;              // [32][8] partial (m,s) after score phase

    // ---- load Q tile (hi/lo, swizzled, cp.async) ----
    {
        const unsigned short* Qh = g_qh + ((size_t)(bh * 1024 + t0)) * 128;
        const unsigned short* Ql = g_ql + ((size_t)(bh * 1024 + t0)) * 128;
#pragma unroll
        for (int it = 0; it < 2; it++) {
            int idx = it * 512 + tid;         // 1024: 512 hi + 512 lo
            int half = idx >> 9;
            uint32_t r = (idx >> 4) & 31, g = idx & 15;
            const unsigned short* src = (half ? Ql : Qh) + r * 128 + g * 8;
            cp16(sb + half * 8192 + swz128(r, g), src);
        }
        CP_COMMIT();
    }

    // score-phase warp mapping: wr = row half (0..1), wc = 16-col group (0..7)
    const int wr = w >> 3, wc = w & 7;
    float bqv[2];
    bqv[0] = g_bq[bh * T_ + t0 + wr * 16 + g8];
    bqv[1] = g_bq[bh * T_ + t0 + wr * 16 + g8 + 8];
    const int tgr0 = t0 + wr * 16 + g8;       // this thread's two rows
    const int tgr1 = tgr0 + 8;

    // online first-softmax state (per thread, per row)
    float m_on[2] = {-3.4e38f, -3.4e38f};
    float s_on[2] = {0.f, 0.f};

    // ==================== score phase ====================
    for (int st = 0; st < NT; st++) {
        const int S0 = st * 128;
        __syncthreads();
        {
            const unsigned short* Kh = g_kh + ((size_t)(bh * 1024 + S0)) * 128;
            const unsigned short* Kl = g_kl + ((size_t)(bh * 1024 + S0)) * 128;
#pragma unroll
            for (int it = 0; it < 8; it++) {
                int idx = it * 512 + tid;     // 4096: 2048 hi + 2048 lo
                int half = idx >> 11;
                uint32_t r = (idx >> 4) & 127, g = idx & 15;
                const unsigned short* src = (half ? Kl : Kh) + r * 128 + g * 8;
                cp16(sb + 16384 + half * 32768 + swz128(r, g), src);
            }
            CP_COMMIT();
            CP_WAIT0();
        }
        __syncthreads();

        float acc[2][4];
#pragma unroll
        for (int j = 0; j < 2; j++)
#pragma unroll
            for (int q = 0; q < 4; q++) acc[j][q] = 0.f;

#pragma unroll
        for (int ks = 0; ks < 8; ks++) {
            uint32_t cbA = (uint32_t)(ks * 2 + a_c);
            uint32_t cbB = (uint32_t)(ks * 2 + b_c);
            uint32_t ah[4], al[4];
            ldsm_x4(ah, aQh + swz128((uint32_t)(wr * 16 + a_r), cbA));
            ldsm_x4(al, aQl + swz128((uint32_t)(wr * 16 + a_r), cbA));
            uint32_t t4[4], bhf[2][2], blf[2][2];
            ldsm_x4(t4, aKh + swz128((uint32_t)(wc * 16 + b_r), cbB));
            bhf[0][0] = t4[0]; bhf[0][1] = t4[1]; bhf[1][0] = t4[2]; bhf[1][1] = t4[3];
            ldsm_x4(t4, aKl + swz128((uint32_t)(wc * 16 + b_r), cbB));
            blf[0][0] = t4[0]; blf[0][1] = t4[1]; blf[1][0] = t4[2]; blf[1][1] = t4[3];
#pragma unroll
            for (int nt = 0; nt < 2; nt++) {
                mma16816(acc[nt], ah, bhf[nt]);
                mma16816(acc[nt], ah, blf[nt]);
                mma16816(acc[nt], al, bhf[nt]);
            }
        }
        // epilogue: scores = 0.25*dot - 0.125*(bq+bk); online max/sum (causal-masked)
        float sv0[4], sv1[4];
        int   sc0[4];
#pragma unroll
        for (int nt = 0; nt < 2; nt++) {
            int col = wc * 16 + nt * 8 + 2 * t2;
            float2 bk2 = *(const float2*)(g_bk + bh * T_ + S0 + col);
            int row = wr * 16 + g8;
            float2 v0, v1;
            v0.x = 0.25f * acc[nt][0] - 0.125f * (bqv[0] + bk2.x);
            v0.y = 0.25f * acc[nt][1] - 0.125f * (bqv[0] + bk2.y);
            v1.x = 0.25f * acc[nt][2] - 0.125f * (bqv[1] + bk2.x);
            v1.y = 0.25f * acc[nt][3] - 0.125f * (bqv[1] + bk2.y);
            *(float2*)(sc + (size_t)row * SC_STRIDE + S0 + col) = v0;
            *(float2*)(sc + (size_t)(row + 8) * SC_STRIDE + S0 + col) = v1;
            sv0[2 * nt] = v0.x; sv0[2 * nt + 1] = v0.y;
            sv1[2 * nt] = v1.x; sv1[2 * nt + 1] = v1.y;
            sc0[2 * nt] = S0 + col; sc0[2 * nt + 1] = S0 + col + 1;
        }
#pragma unroll
        for (int rr = 0; rr < 2; rr++) {
            const int tg = rr ? tgr1 : tgr0;
            float* sv = rr ? sv1 : sv0;
            float x0 = (sc0[0] <= tg) ? sv[0] : -1e38f;
            float x1 = (sc0[1] <= tg) ? sv[1] : -1e38f;
            float x2 = (sc0[2] <= tg) ? sv[2] : -1e38f;
            float x3 = (sc0[3] <= tg) ? sv[3] : -1e38f;
            float cm = fmaxf(fmaxf(x0, x1), fmaxf(x2, x3));
            float cs = fexp(x0 - cm) + fexp(x1 - cm) + fexp(x2 - cm) + fexp(x3 - cm);
            osm_merge(m_on[rr], s_on[rr], cm, cs);
        }
    }
    __syncthreads();

    // reduce online (m,s) across t2 group (4 lanes per row) and store per-warp partials
    {
#pragma unroll
        for (int rr = 0; rr < 2; rr++) {
#pragma unroll
            for (int o = 1; o < 4; o <<= 1) {
                float om = __shfl_xor_sync(0xffffffffu, m_on[rr], o);
                float os = __shfl_xor_sync(0xffffffffu, s_on[rr], o);
                osm_merge(m_on[rr], s_on[rr], om, os);
            }
        }
        if (t2 == 0) {
            part[(wr * 16 + g8) * 8 + wc] = make_float2(m_on[0], s_on[0]);
            part[(wr * 16 + g8 + 8) * 8 + wc] = make_float2(m_on[1], s_on[1]);
        }
    }
    __syncthreads();

    // ==================== softmax: merge partials -> scan/decay -> final exp ====================
    {
        float g = gammas[h];
        float gamma = -(fmaxf(g, 0.f) + log1pf(__expf(-fabsf(g))));

        const int r0 = w, r1 = w + 16;
        const int tg0 = t0 + r0, tg1 = t0 + r1;
        float* row0 = sc + (size_t)r0 * SC_STRIDE;
        float* row1 = sc + (size_t)r1 * SC_STRIDE;
        const int L0 = tg0 + 1, L1 = tg1 + 1;      // L1 > L0

        float pm0 = -3.4e38f, ps0 = 0.f, pm1 = -3.4e38f, ps1 = 0.f;
        if (lane < 8) {
            float2 p0 = part[r0 * 8 + lane];
            float2 p1 = part[r1 * 8 + lane];
            pm0 = p0.x; ps0 = p0.y;
            pm1 = p1.x; ps1 = p1.y;
        }
#pragma unroll
        for (int o = 1; o < 8; o <<= 1) {
            float om0 = __shfl_xor_sync(0xffffffffu, pm0, o);
            float os0 = __shfl_xor_sync(0xffffffffu, ps0, o);
            float om1 = __shfl_xor_sync(0xffffffffu, pm1, o);
            float os1 = __shfl_xor_sync(0xffffffffu, ps1, o);
            osm_merge(pm0, ps0, om0, os0);
            osm_merge(pm1, ps1, om1, os1);
        }
        const float m0 = __shfl_sync(0xffffffffu, pm0, 0);
        const float sum0 = __shfl_sync(0xffffffffu, ps0, 0);
        const float m1 = __shfl_sync(0xffffffffu, pm1, 0);
        const float sum1 = __shfl_sync(0xffffffffu, ps1, 0);
        const float inv0 = 1.f / sum0, inv1 = 1.f / sum1;

        float carry0 = 0.f, carry1 = 0.f;
        float mm0 = -3.4e38f, mm1 = -3.4e38f;
        const int nch = (L1 + 31) >> 5;
        for (int c = 0; c < nch; c++) {
            int s = c * 32 + lane;
            bool v0 = (s < L0), v1 = (s < L1);
            float x0 = v0 ? row0[s] : 0.f;
            float x1 = v1 ? row1[s] : 0.f;
            float e0 = v0 ? fexp(x0 - m0) * inv0 : 0.f;
            float e1 = v1 ? fexp(x1 - m1) * inv1 : 0.f;
            float s0v = e0, s1v = e1;
#pragma unroll
            for (int o = 1; o < 32; o <<= 1) {
                float n0 = __shfl_up_sync(0xffffffffu, s0v, o);
                float n1 = __shfl_up_sync(0xffffffffu, s1v, o);
                if (lane >= o) { s0v += n0; s1v += n1; }
            }
            float cum0 = carry0 + s0v, cum1 = carry1 + s1v;
            carry0 += __shfl_sync(0xffffffffu, s0v, 31);
            carry1 += __shfl_sync(0xffffffffu, s1v, 31);
            if (v0) {
                float pos = (float)(tg0 - s);
                float ds = fsqrt(fmaxf((1.f - cum0) * pos, 0.f));
                float eff = fminf(fmaxf(fexp(ds * gamma), 1e-5f), 1e5f);
                float y = x0 * eff;
                row0[s] = y;
                mm0 = fmaxf(mm0, y);
            }
            if (v1) {
                float pos = (float)(tg1 - s);
                float ds = fsqrt(fmaxf((1.f - cum1) * pos, 0.f));
                float eff = fminf(fmaxf(fexp(ds * gamma), 1e-5f), 1e5f);
                float y = x1 * eff;
                row1[s] = y;
                mm1 = fmaxf(mm1, y);
            }
        }
        mm0 = wredmax(mm0); mm1 = wredmax(mm1);

        float s20 = 0.f, s21 = 0.f;
        for (int s = lane; s < L1; s += 32) {
            if (s < L0) {
                float e = fexp(row0[s] - mm0);
                row0[s] = e;
                s20 += e;
            }
            float e = fexp(row1[s] - mm1);
            row1[s] = e;
            s21 += e;
        }
        s20 = wredsum(s20); s21 = wredsum(s21);
        if (lane == 0) {
            row0[1024] = (tg0 == 0) ? 0.f : 1.f / s20;   // inv2 in row padding
            row1[1024] = (tg1 == 0) ? 0.f : 1.f / s21;
        }
    }
    __syncthreads();

    // ==================== PV phase (mma.sync, 16 warps, cp.async V prefetch) ====================
    const int wm = w >> 3;          // 0..1 (m16 tile)
    const int wn = w & 7;           // 0..7 (8-d column group)
    float am[4], acv[4];
#pragma unroll
    for (int q = 0; q < 4; q++) { am[q] = 0.f; acv[q] = 0.f; }

    const unsigned short* Vmh = g_vmh + (size_t)bh * DK_ * T_;
    const unsigned short* Vml = g_vml + (size_t)bh * DK_ * T_;
    const unsigned short* Vch = g_vch + (size_t)bh * DK_ * T_;
    const unsigned short* Vcl = g_vcl + (size_t)bh * DK_ * T_;

    const uint32_t x2row = (uint32_t)(wn * 8 + (lane & 7));
    const uint32_t x2half = (uint32_t)((lane >> 3) & 1);

    for (int st = 0; st < NT; st++) {
        const int S0 = st * 128;
        __syncthreads();
        // issue V tile cp.asyncs FIRST (they land in stg[32K..96K), disjoint from P region)
#pragma unroll
        for (int it = 0; it < 8; it++) {
            int idx = it * 512 + tid;
            int arr = idx >> 10;
            uint32_t r = (uint32_t)((idx >> 4) & 63), gg = (uint32_t)(idx & 15);
            const unsigned short* src =
                (arr == 0 ? Vmh : arr == 1 ? Vml : arr == 2 ? Vch : Vcl) + (size_t)r * T_ + S0 + gg * 8;
            cp16(sb + 32768 + arr * 16384 + swz128(r, gg), src);
        }
        CP_COMMIT();
        // convert P chunk -> bf16 hi/lo + P^2 hi/lo (overlaps V loads)
        {
            int idx = tid;
            uint32_t r = (uint32_t)(idx >> 4), gg = (uint32_t)(idx & 15);
            const float* prow = sc + (size_t)r * SC_STRIDE;
            const float inv2 = prow[1024];
            const int tg = t0 + (int)r;
            unsigned short ph[8], pl[8], qh2[8], ql2[8];
#pragma unroll
            for (int j = 0; j < 8; j++) {
                int s = S0 + (int)gg * 8 + j;
                float p = (s <= tg) ? prow[s] * inv2 : 0.f;
                bf16split(p, ph[j], pl[j]);
                bf16split(p * p, qh2[j], ql2[j]);
            }
            uint32_t so = swz128(r, gg);
            *(uint4*)(stg + so) = *(uint4*)ph;
            *(uint4*)(stg + 8192 + so) = *(uint4*)pl;
            *(uint4*)(stg + 16384 + so) = *(uint4*)qh2;
            *(uint4*)(stg + 24576 + so) = *(uint4*)ql2;
        }
        CP_WAIT0();
        __syncthreads();

#pragma unroll
        for (int ks = 0; ks < 8; ks++) {
            uint32_t cbA = (uint32_t)(ks * 2 + a_c);
            uint32_t cbB2 = (uint32_t)(ks * 2 + x2half);
            uint32_t ap[4], al2[4], a2p[4], a2l[4];
            uint32_t ra = (uint32_t)(wm * 16 + a_r);
            ldsm_x4(ap,  aPh  + swz128(ra, cbA));
            ldsm_x4(al2, aPl  + swz128(ra, cbA));
            ldsm_x4(a2p, aP2h + swz128(ra, cbA));
            ldsm_x4(a2l, aP2l + swz128(ra, cbA));

            uint32_t bmh[2], bml[2], bch[2], bcl[2];
            uint32_t boff = swz128(x2row, cbB2);
            ldsm_x2(bmh, aVmh + boff);
            ldsm_x2(bml, aVml + boff);
            ldsm_x2(bch, aVch + boff);
            ldsm_x2(bcl, aVcl + boff);

            mma16816(am, ap, bmh);
            mma16816(am, ap, bml);
            mma16816(am, al2, bmh);
            mma16816(acv, a2p, bch);
            mma16816(acv, a2p, bcl);
            mma16816(acv, a2l, bch);
        }
    }

    // write outputs directly as bf16 hi/lo (fused split_c)
    {
        int col = h * 64 + wn * 8 + 2 * t2;
#pragma unroll
        for (int half = 0; half < 2; half++) {
            int trow = t0 + wm * 16 + g8 + half * 8;
            size_t o = (size_t)(b * 1024 + trow) * 512 + col;
            unsigned short mh0, ml0, mh1, ml1, ch0, cl0, ch1, cl1;
            bf16split(am[half * 2],      mh0, ml0);
            bf16split(am[half * 2 + 1],  mh1, ml1);
            bf16split(acv[half * 2],     ch0, cl0);
            bf16split(acv[half * 2 + 1], ch1, cl1);
            *(ushort2*)((unsigned short*)&g_chi[0][0] + o) = make_ushort2(mh0, mh1);
            *(ushort2*)((unsigned short*)&g_clo[0][0] + o) = make_ushort2(ml0, ml1);
            *(ushort2*)((unsigned short*)&g_chi[1][0] + o) = make_ushort2(ch0, ch1);
            *(ushort2*)((unsigned short*)&g_clo[1][0] + o) = make_ushort2(cl0, cl1);
        }
    }
}

// ---------------- launch ----------------
extern "C" void kernel_launch(void* const* d_in, const int* in_sizes, int n_in,
                              void* d_out, int out_size)
{
    const float* q_mean  = (const float*)d_in[0];
    const float* q_cov   = (const float*)d_in[1];
    const float* k_mean  = (const float*)d_in[2];
    const float* k_cov   = (const float*)d_in[3];
    const float* v_mean  = (const float*)d_in[4];
    const float* v_cov   = (const float*)d_in[5];
    const float* Wk_mean = (const float*)d_in[6];
    const float* bk_mean = (const float*)d_in[7];
    const float* Wk_cov  = (const float*)d_in[8];
    const float* bk_cov  = (const float*)d_in[9];
    const float* Wv_mean = (const float*)d_in[10];
    const float* bv_mean = (const float*)d_in[11];
    const float* Wv_cov  = (const float*)d_in[12];
    const float* bv_cov  = (const float*)d_in[13];
    const float* Wo_mean = (const float*)d_in[14];
    const float* bo_mean = (const float*)d_in[15];
    const float* Wo_cov  = (const float*)d_in[16];
    const float* bo_cov  = (const float*)d_in[17];
    const float* gammas  = (const float*)d_in[18];
    float* out = (float*)d_out;

    // launch 0: projection GEMMs (fp32 inputs, split fused into staging)
    cudaFuncSetAttribute(gemm_mma, cudaFuncAttributeMaxDynamicSharedMemorySize, GEMM_SMEM);
    GemmArgs gp;
    gp.bias[0] = bk_mean; gp.bias[1] = bk_cov; gp.bias[2] = bv_mean;
    gp.bias[3] = bv_cov;  gp.bias[4] = bo_mean; gp.bias[5] = bo_cov;
    gp.Af[0] = q_mean; gp.Af[1] = q_cov; gp.Af[2] = k_mean;
    gp.Af[3] = k_cov;  gp.Af[4] = v_mean; gp.Af[5] = v_cov;
    gp.Wf[0] = Wk_mean; gp.Wf[1] = Wk_cov; gp.Wf[2] = Wv_mean;
    gp.Wf[3] = Wv_cov;  gp.Wf[4] = Wo_mean; gp.Wf[5] = Wo_cov;
    gp.out = nullptr; gp.is_out = 0;
    gemm_mma<<<dim3(4, 64, 6), 256, GEMM_SMEM>>>(gp);

    // launch 1: pack Q/K/V (+rowsums)
    pack_all<<<8192, 256>>>();

    // launch 2: fused attention
    cudaFuncSetAttribute(attn_kernel, cudaFuncAttributeMaxDynamicSharedMemorySize, ATTN_SMEM);
    attn_kernel<<<dim3(32, 64), 512, ATTN_SMEM>>>(gammas);

    // launch 3: output GEMMs
    GemmArgs go = gp;
    go.out = out; go.is_out = 1;
    gemm_mma<<<dim3(4, 64, 2), 256, GEMM_SMEM>>>(go);
}

// round 17
// speedup vs baseline: 1.0940x; 1.0940x over previous
#include <cuda_runtime.h>
#include <cuda_bf16.h>
#include <math.h>
#include <stdint.h>

// Problem constants
#define B_  8
#define T_  1024
#define D_  512
#define H_  8
#define DK_ 64
#define BT_ 8192      // B*T
#define BH_ 64        // B*H

// single dynamic-smem symbol (gemm + attention)
extern __shared__ char dsmem[];

// ---------------- scratch (device globals; no allocation allowed) ----------------
__device__ float g_proj[6][BT_ * D_];        // 0:qm 1:qc 2:km 3:kc 4:vm 5:vc
__device__ __nv_bfloat16 g_chi[2][BT_ * D_];
__device__ __nv_bfloat16 g_clo[2][BT_ * D_];
// attention operands (bf16 hi/lo)
__device__ unsigned short g_qh[BH_ * T_ * 128];   // [bh][t][dcat] K-major
__device__ unsigned short g_ql[BH_ * T_ * 128];
__device__ unsigned short g_kh[BH_ * T_ * 128];
__device__ unsigned short g_kl[BH_ * T_ * 128];
__device__ unsigned short g_vmh[BH_ * DK_ * T_]; // [bh][d][s] (V transposed)
__device__ unsigned short g_vml[BH_ * DK_ * T_];
__device__ unsigned short g_vch[BH_ * DK_ * T_];
__device__ unsigned short g_vcl[BH_ * DK_ * T_];
__device__ float g_bq[BH_ * T_];
__device__ float g_bk[BH_ * T_];

// ================= fast transcendentals on FMA/ALU pipes =================
__device__ __forceinline__ float fexp(float x)
{
    x = fmaxf(x, -80.0f);
    float t = x * 1.4426950408889634f;            // log2(e)
    float nf = t + 12582912.0f;                   // 1.5*2^23 round-to-nearest
    int   ei = __float_as_int(nf) - 0x4b400000;
    float n  = nf - 12582912.0f;
    float f  = t - n;                             // f in [-0.5, 0.5]
    float p  = 1.3338464e-3f;
    p = fmaf(p, f, 9.6180203e-3f);
    p = fmaf(p, f, 5.5503614e-2f);
    p = fmaf(p, f, 2.4022647e-1f);
    p = fmaf(p, f, 6.9314718e-1f);
    p = fmaf(p, f, 1.0f);
    return __int_as_float(__float_as_int(p) + (ei << 23));
}
__device__ __forceinline__ float fsqrt(float z)
{
    z = fmaxf(z, 1e-30f);
    float r = __int_as_float(0x5f3759df - (__float_as_int(z) >> 1));
    r = r * fmaf(-0.5f * z * r, r, 1.5f);
    r = r * fmaf(-0.5f * z * r, r, 1.5f);
    return z * r;
}

// ================= mma.sync helpers =================
__device__ __forceinline__ uint32_t smem_u32(const void* p) {
    uint32_t a;
    asm("{ .reg .u64 t; cvta.to.shared.u64 t, %1; cvt.u32.u64 %0, t; }" : "=r"(a) : "l"(p));
    return a;
}
__device__ __forceinline__ void ldsm_x4(uint32_t* r, uint32_t addr) {
    asm volatile("ldmatrix.sync.aligned.m8n8.x4.shared.b16 {%0,%1,%2,%3}, [%4];"
                 : "=r"(r[0]), "=r"(r[1]), "=r"(r[2]), "=r"(r[3]) : "r"(addr));
}
__device__ __forceinline__ void ldsm_x2(uint32_t* r, uint32_t addr) {
    asm volatile("ldmatrix.sync.aligned.m8n8.x2.shared.b16 {%0,%1}, [%2];"
                 : "=r"(r[0]), "=r"(r[1]) : "r"(addr));
}
__device__ __forceinline__ void mma16816(float* c, const uint32_t* a, const uint32_t* b) {
    asm volatile("mma.sync.aligned.m16n8k16.row.col.f32.bf16.bf16.f32 "
                 "{%0,%1,%2,%3}, {%4,%5,%6,%7}, {%8,%9}, {%0,%1,%2,%3};"
                 : "+f"(c[0]), "+f"(c[1]), "+f"(c[2]), "+f"(c[3])
                 : "r"(a[0]), "r"(a[1]), "r"(a[2]), "r"(a[3]), "r"(b[0]), "r"(b[1]));
}
// swizzle for [R][64]-bf16 tiles (128B rows) — gemm BK=64
__device__ __forceinline__ uint32_t swzK(uint32_t r, uint32_t g) {
    return r * 128u + ((g ^ (r & 7u)) << 4);
}
// swizzle for [R][128]-bf16 tiles (256B rows) — attn
__device__ __forceinline__ uint32_t swz128(uint32_t r, uint32_t g) {
    return r * 256u + ((g ^ (r & 7u)) << 4);
}
__device__ __forceinline__ void bf16split(float x, unsigned short& h, unsigned short& l) {
    __nv_bfloat16 hb = __float2bfloat16(x);
    __nv_bfloat16 lb = __float2bfloat16(x - __bfloat162float(hb));
    h = __bfloat16_as_ushort(hb);
    l = __bfloat16_as_ushort(lb);
}
// split 8 consecutive fp32 into hi/lo uint4 pair
__device__ __forceinline__ void split8(const float* src, uint4& hi, uint4& lo)
{
    float4 a0 = *(const float4*)src;
    float4 a1 = *(const float4*)(src + 4);
    float x[8] = {a0.x, a0.y, a0.z, a0.w, a1.x, a1.y, a1.z, a1.w};
    unsigned short hh[8], ll[8];
#pragma unroll
    for (int i = 0; i < 8; i++) bf16split(x[i], hh[i], ll[i]);
    hi = *(uint4*)hh;
    lo = *(uint4*)ll;
}
// online softmax merge: (m,s) += (cm, cs)
__device__ __forceinline__ void osm_merge(float& m, float& s, float cm, float cs)
{
    float nm = fmaxf(m, cm);
    s = s * fexp(m - nm) + cs * fexp(cm - nm);
    m = nm;
}

// ================= bf16x3 GEMM via mma.sync, BK=64, fused input split =================
#define GEMM_SMEM 65536
struct GemmArgs { const float* bias[6]; const float* Af[6]; const float* Wf[6]; float* out; int is_out; };

__global__ void __launch_bounds__(256, 2) gemm_mma(GemmArgs ga)
{
    char* smem = dsmem;

    const int z = blockIdx.z;
    const int n0 = blockIdx.x * 128;
    const int m0 = blockIdx.y * 128;
    const int tid = threadIdx.x;
    const int lane = tid & 31;
    const int w = tid >> 5;
    const int wm = w >> 2;
    const int wn = w & 3;

    const __nv_bfloat16 *Ah = nullptr, *Al = nullptr;
    const float *Af = nullptr, *Wf;
    const float* bias;
    float* C;
    if (ga.is_out) {
        Ah = g_chi[z]; Al = g_clo[z];
        Wf = ga.Wf[4 + z];
        bias = ga.bias[4 + z];
        C = ga.out + (size_t)z * BT_ * D_;
    } else {
        int ws = (z < 4) ? (z & 1) : (z - 2);
        Af = ga.Af[z];
        Wf = ga.Wf[ws];
        bias = ga.bias[ws];
        C = &g_proj[z][0];
    }

    const uint32_t sb = smem_u32(smem);
    const uint32_t bAhi = sb, bAlo = sb + 16384, bWhi = sb + 32768, bWlo = sb + 49152;
    char* pAhi = smem;
    char* pAlo = smem + 16384;
    char* pWhi = smem + 32768;
    char* pWlo = smem + 49152;

    float acc[4][4][4];
#pragma unroll
    for (int i = 0; i < 4; i++)
#pragma unroll
        for (int j = 0; j < 4; j++)
#pragma unroll
            for (int q = 0; q < 4; q++) acc[i][j][q] = 0.f;

    const int a_r = lane & 15, a_c = lane >> 4;
    const int b_r = (lane & 7) + ((lane >> 4) << 3);
    const int b_c = (lane >> 3) & 1;

    for (int kt = 0; kt < 512; kt += 64) {
        __syncthreads();
#pragma unroll
        for (int i = 0; i < 4; i++) {
            int idx = i * 256 + tid;
            uint32_t r = (uint32_t)(idx >> 3), g = (uint32_t)(idx & 7);
            uint32_t so = swzK(r, g);
            size_t goA = (size_t)(m0 + r) * 512 + kt + g * 8;
            size_t goW = (size_t)(n0 + r) * 512 + kt + g * 8;
            uint4 hi, lo;
            split8(Wf + goW, hi, lo);
            *(uint4*)(pWhi + so) = hi;
            *(uint4*)(pWlo + so) = lo;
            if (ga.is_out) {
                *(uint4*)(pAhi + so) = *(const uint4*)(Ah + goA);
                *(uint4*)(pAlo + so) = *(const uint4*)(Al + goA);
            } else {
                split8(Af + goA, hi, lo);
                *(uint4*)(pAhi + so) = hi;
                *(uint4*)(pAlo + so) = lo;
            }
        }
        __syncthreads();

#pragma unroll
        for (int ks = 0; ks < 4; ks++) {
            uint32_t bhi[4][2], blo[4][2];
#pragma unroll
            for (int pr = 0; pr < 2; pr++) {
                uint32_t r = (uint32_t)(wn * 32 + pr * 16 + b_r);
                uint32_t cb = (uint32_t)(ks * 2 + b_c);
                uint32_t t[4];
                ldsm_x4(t, bWhi + swzK(r, cb));
                bhi[2 * pr][0] = t[0]; bhi[2 * pr][1] = t[1];
                bhi[2 * pr + 1][0] = t[2]; bhi[2 * pr + 1][1] = t[3];
                ldsm_x4(t, bWlo + swzK(r, cb));
                blo[2 * pr][0] = t[0]; blo[2 * pr][1] = t[1];
                blo[2 * pr + 1][0] = t[2]; blo[2 * pr + 1][1] = t[3];
            }
            uint32_t a[4][4];
            {
                uint32_t cb = (uint32_t)(ks * 2 + a_c);
#pragma unroll
                for (int mt = 0; mt < 4; mt++) {
                    uint32_t r = (uint32_t)(wm * 64 + mt * 16 + a_r);
                    ldsm_x4(a[mt], bAhi + swzK(r, cb));
                }
            }
#pragma unroll
            for (int mt = 0; mt < 4; mt++)
#pragma unroll
                for (int nt = 0; nt < 4; nt++) {
                    mma16816(acc[mt][nt], a[mt], bhi[nt]);
                    mma16816(acc[mt][nt], a[mt], blo[nt]);
                }
            {
                uint32_t cb = (uint32_t)(ks * 2 + a_c);
#pragma unroll
                for (int mt = 0; mt < 4; mt++) {
                    uint32_t r = (uint32_t)(wm * 64 + mt * 16 + a_r);
                    ldsm_x4(a[mt], bAlo + swzK(r, cb));
                }
            }
#pragma unroll
            for (int mt = 0; mt < 4; mt++)
#pragma unroll
                for (int nt = 0; nt < 4; nt++)
                    mma16816(acc[mt][nt], a[mt], bhi[nt]);
        }
    }

    const int g8 = lane >> 2;
    const int t2 = lane & 3;
#pragma unroll
    for (int nt = 0; nt < 4; nt++) {
        int col = n0 + wn * 32 + nt * 8 + 2 * t2;
        float2 b2 = *(const float2*)(bias + col);
#pragma unroll
        for (int mt = 0; mt < 4; mt++) {
            int row0 = m0 + wm * 64 + mt * 16 + g8;
            float2 v0 = make_float2(acc[mt][nt][0] + b2.x, acc[mt][nt][1] + b2.y);
            float2 v1 = make_float2(acc[mt][nt][2] + b2.x, acc[mt][nt][3] + b2.y);
            *(float2*)(C + (size_t)row0 * 512 + col) = v0;
            *(float2*)(C + (size_t)(row0 + 8) * 512 + col) = v1;
        }
    }
}

// ---------------- merged pack kernel (unchanged) ----------------
__global__ void pack_all()
{
    __shared__ float tile[32][65];
    int tid = threadIdx.x;

    if (blockIdx.x < 4096) {
        int idx = blockIdx.x * 256 + tid;
        int g = idx & 15;
        int t = (idx >> 4) & 1023;
        int bh = idx >> 14;
        int b = bh >> 3, h = bh & 7;
        size_t base = (size_t)(b * 1024 + t) * 512 + h * 64;

        float qv[8], kv[8];
        float bq_part = 0.f, bk_part = 0.f;
        if (g < 8) {
#pragma unroll
            for (int j = 0; j < 8; j++) {
                qv[j] = g_proj[0][base + g * 8 + j];
                kv[j] = g_proj[2][base + g * 8 + j];
                bq_part += qv[j] * qv[j];
                bk_part += kv[j] * kv[j];
            }
        } else {
#pragma unroll
            for (int j = 0; j < 8; j++) {
                float qr = g_proj[1][base + (g - 8) * 8 + j];
                float kr = g_proj[3][base + (g - 8) * 8 + j];
                bq_part += qr;
                bk_part += kr;
                qv[j] = fsqrt(fmaxf(qr, 1e-24f));
                kv[j] = fsqrt(fmaxf(kr, 1e-24f));
            }
        }
#pragma unroll
        for (int o = 8; o; o >>= 1) {
            bq_part += __shfl_xor_sync(0xffffffffu, bq_part, o);
            bk_part += __shfl_xor_sync(0xffffffffu, bk_part, o);
        }
        if (g == 0) {
            g_bq[bh * T_ + t] = bq_part;
            g_bk[bh * T_ + t] = bk_part;
        }

        unsigned short qh8[8], ql8[8], kh8[8], kl8[8];
#pragma unroll
        for (int j = 0; j < 8; j++) {
            bf16split(qv[j], qh8[j], ql8[j]);
            bf16split(kv[j], kh8[j], kl8[j]);
        }
        size_t o = ((size_t)(bh * 1024 + t)) * 128 + g * 8;
        *(uint4*)(g_qh + o) = *(uint4*)qh8;
        *(uint4*)(g_ql + o) = *(uint4*)ql8;
        *(uint4*)(g_kh + o) = *(uint4*)kh8;
        *(uint4*)(g_kl + o) = *(uint4*)kl8;
    } else {
        int bx = blockIdx.x - 4096;
        int s0 = (bx & 31) * 32;
        int z = (bx >> 5) & 1;
        int bh = bx >> 6;
        int b = bh >> 3, h = bh & 7;
        const float* src = g_proj[4 + z];

#pragma unroll
        for (int e = 0; e < 8; e++) {
            int idx = e * 256 + tid;
            int sl = idx >> 6, d = idx & 63;
            tile[sl][d] = src[(size_t)(b * 1024 + s0 + sl) * 512 + h * 64 + d];
        }
        __syncthreads();
        unsigned short* dh = z ? g_vch : g_vmh;
        unsigned short* dl = z ? g_vcl : g_vml;
#pragma unroll
        for (int e = 0; e < 8; e++) {
            int idx = e * 256 + tid;
            int d = idx >> 5, sl = idx & 31;
            unsigned short hh, ll;
            bf16split(tile[sl][d], hh, ll);
            size_t o = ((size_t)(bh * 64 + d)) * 1024 + s0 + sl;
            dh[o] = hh;
            dl[o] = ll;
        }
    }
}

// ---------------- fused attention: TR=32, 512 threads, online first-softmax ----------------
#define TR 32
#define SC_STRIDE 1028
#define STG_OFF (32 * SC_STRIDE * 4)          // 131584
#define ATTN_SMEM (STG_OFF + 98304)           // 229888

__device__ __forceinline__ float wredmax(float v)
{
#pragma unroll
    for (int o = 16; o; o >>= 1) v = fmaxf(v, __shfl_xor_sync(0xffffffffu, v, o));
    return v;
}
__device__ __forceinline__ float wredsum(float v)
{
#pragma unroll
    for (int o = 16; o; o >>= 1) v += __shfl_xor_sync(0xffffffffu, v, o);
    return v;
}

__global__ void __launch_bounds__(512, 1) attn_kernel(const float* __restrict__ gammas)
{
    char* smem = dsmem;
    float* sc = (float*)smem;
    char* stg = smem + STG_OFF;

    // 1D grid, globally heavy-first: all bh's heaviest tiles lead, lightest trail.
    const int bid = blockIdx.x;
    const int tile = 31 - (bid >> 6);
    const int bh = bid & 63;
    const int t0 = tile * TR;
    const int tid = threadIdx.x;
    const int lane = tid & 31, w = tid >> 5;
    const int NT = (t0 + TR + 127) / 128;
    const int b = bh >> 3, h = bh & 7;

    const int a_r = lane & 15, a_c = lane >> 4;
    const int b_r = (lane & 7) + ((lane >> 4) << 3);
    const int b_c = (lane >> 3) & 1;
    const int g8 = lane >> 2, t2 = lane & 3;

    // staging addresses
    const uint32_t sb = smem_u32(stg);
    const uint32_t aQh = sb, aQl = sb + 8192, aKh = sb + 16384, aKl = sb + 49152;
    const uint32_t aPh = sb, aPl = sb + 8192, aP2h = sb + 16384, aP2l = sb + 24576;
    const uint32_t aVmh = sb + 32768, aVml = sb + 49152, aVch = sb + 65536, aVcl = sb + 81920;
    float2* part = (float2*)stg;              // [32][8] partial (m,s) after score phase

    // ---- load Q tile (hi/lo, swizzled) ----
    {
        const unsigned short* Qh = g_qh + ((size_t)(bh * 1024 + t0)) * 128;
        const unsigned short* Ql = g_ql + ((size_t)(bh * 1024 + t0)) * 128;
#pragma unroll
        for (int it = 0; it < 2; it++) {
            int idx = it * 512 + tid;         // 1024: 512 hi + 512 lo
            int half = idx >> 9;
            uint32_t r = (idx >> 4) & 31, g = idx & 15;
            const unsigned short* src = (half ? Ql : Qh) + r * 128 + g * 8;
            *(uint4*)(stg + half * 8192 + swz128(r, g)) = *(const uint4*)src;
        }
    }

    // score-phase warp mapping: wr = row half (0..1), wc = 16-col group (0..7)
    const int wr = w >> 3, wc = w & 7;
    float bqv[2];
    bqv[0] = g_bq[bh * T_ + t0 + wr * 16 + g8];
    bqv[1] = g_bq[bh * T_ + t0 + wr * 16 + g8 + 8];
    const int tgr0 = t0 + wr * 16 + g8;       // this thread's two rows
    const int tgr1 = tgr0 + 8;

    // online first-softmax state (per thread, per row)
    float m_on[2] = {-3.4e38f, -3.4e38f};
    float s_on[2] = {0.f, 0.f};

    // ==================== score phase ====================
    for (int st = 0; st < NT; st++) {
        const int S0 = st * 128;
        __syncthreads();
        {
            const unsigned short* Kh = g_kh + ((size_t)(bh * 1024 + S0)) * 128;
            const unsigned short* Kl = g_kl + ((size_t)(bh * 1024 + S0)) * 128;
#pragma unroll
            for (int it = 0; it < 8; it++) {
                int idx = it * 512 + tid;     // 4096: 2048 hi + 2048 lo
                int half = idx >> 11;
                uint32_t r = (idx >> 4) & 127, g = idx & 15;
                const unsigned short* src = (half ? Kl : Kh) + r * 128 + g * 8;
                *(uint4*)(stg + 16384 + half * 32768 + swz128(r, g)) = *(const uint4*)src;
            }
        }
        __syncthreads();

        float acc[2][4];
#pragma unroll
        for (int j = 0; j < 2; j++)
#pragma unroll
            for (int q = 0; q < 4; q++) acc[j][q] = 0.f;

#pragma unroll
        for (int ks = 0; ks < 8; ks++) {
            uint32_t cbA = (uint32_t)(ks * 2 + a_c);
            uint32_t cbB = (uint32_t)(ks * 2 + b_c);
            uint32_t ah[4], al[4];
            ldsm_x4(ah, aQh + swz128((uint32_t)(wr * 16 + a_r), cbA));
            ldsm_x4(al, aQl + swz128((uint32_t)(wr * 16 + a_r), cbA));
            uint32_t t4[4], bhf[2][2], blf[2][2];
            ldsm_x4(t4, aKh + swz128((uint32_t)(wc * 16 + b_r), cbB));
            bhf[0][0] = t4[0]; bhf[0][1] = t4[1]; bhf[1][0] = t4[2]; bhf[1][1] = t4[3];
            ldsm_x4(t4, aKl + swz128((uint32_t)(wc * 16 + b_r), cbB));
            blf[0][0] = t4[0]; blf[0][1] = t4[1]; blf[1][0] = t4[2]; blf[1][1] = t4[3];
#pragma unroll
            for (int nt = 0; nt < 2; nt++) {
                mma16816(acc[nt], ah, bhf[nt]);
                mma16816(acc[nt], ah, blf[nt]);
                mma16816(acc[nt], al, bhf[nt]);
            }
        }
        // epilogue: scores = 0.25*dot - 0.125*(bq+bk); online max/sum (causal-masked)
        float sv0[4], sv1[4];
        int   sc0[4];
#pragma unroll
        for (int nt = 0; nt < 2; nt++) {
            int col = wc * 16 + nt * 8 + 2 * t2;
            float2 bk2 = *(const float2*)(g_bk + bh * T_ + S0 + col);
            int row = wr * 16 + g8;
            float2 v0, v1;
            v0.x = 0.25f * acc[nt][0] - 0.125f * (bqv[0] + bk2.x);
            v0.y = 0.25f * acc[nt][1] - 0.125f * (bqv[0] + bk2.y);
            v1.x = 0.25f * acc[nt][2] - 0.125f * (bqv[1] + bk2.x);
            v1.y = 0.25f * acc[nt][3] - 0.125f * (bqv[1] + bk2.y);
            *(float2*)(sc + (size_t)row * SC_STRIDE + S0 + col) = v0;
            *(float2*)(sc + (size_t)(row + 8) * SC_STRIDE + S0 + col) = v1;
            sv0[2 * nt] = v0.x; sv0[2 * nt + 1] = v0.y;
            sv1[2 * nt] = v1.x; sv1[2 * nt + 1] = v1.y;
            sc0[2 * nt] = S0 + col; sc0[2 * nt + 1] = S0 + col + 1;
        }
#pragma unroll
        for (int rr = 0; rr < 2; rr++) {
            const int tg = rr ? tgr1 : tgr0;
            float* sv = rr ? sv1 : sv0;
            float x0 = (sc0[0] <= tg) ? sv[0] : -1e38f;
            float x1 = (sc0[1] <= tg) ? sv[1] : -1e38f;
            float x2 = (sc0[2] <= tg) ? sv[2] : -1e38f;
            float x3 = (sc0[3] <= tg) ? sv[3] : -1e38f;
            float cm = fmaxf(fmaxf(x0, x1), fmaxf(x2, x3));
            float cs = fexp(x0 - cm) + fexp(x1 - cm) + fexp(x2 - cm) + fexp(x3 - cm);
            osm_merge(m_on[rr], s_on[rr], cm, cs);
        }
    }
    __syncthreads();

    // reduce online (m,s) across t2 group (4 lanes per row) and store per-warp partials
    {
#pragma unroll
        for (int rr = 0; rr < 2; rr++) {
#pragma unroll
            for (int o = 1; o < 4; o <<= 1) {
                float om = __shfl_xor_sync(0xffffffffu, m_on[rr], o);
                float os = __shfl_xor_sync(0xffffffffu, s_on[rr], o);
                osm_merge(m_on[rr], s_on[rr], om, os);
            }
        }
        if (t2 == 0) {
            part[(wr * 16 + g8) * 8 + wc] = make_float2(m_on[0], s_on[0]);
            part[(wr * 16 + g8 + 8) * 8 + wc] = make_float2(m_on[1], s_on[1]);
        }
    }
    __syncthreads();

    // ==================== softmax: merge partials -> scan/decay -> final exp ====================
    {
        float g = gammas[h];
        float gamma = -(fmaxf(g, 0.f) + log1pf(__expf(-fabsf(g))));

        const int r0 = w, r1 = w + 16;
        const int tg0 = t0 + r0, tg1 = t0 + r1;
        float* row0 = sc + (size_t)r0 * SC_STRIDE;
        float* row1 = sc + (size_t)r1 * SC_STRIDE;
        const int L0 = tg0 + 1, L1 = tg1 + 1;      // L1 > L0

        float pm0 = -3.4e38f, ps0 = 0.f, pm1 = -3.4e38f, ps1 = 0.f;
        if (lane < 8) {
            float2 p0 = part[r0 * 8 + lane];
            float2 p1 = part[r1 * 8 + lane];
            pm0 = p0.x; ps0 = p0.y;
            pm1 = p1.x; ps1 = p1.y;
        }
#pragma unroll
        for (int o = 1; o < 8; o <<= 1) {
            float om0 = __shfl_xor_sync(0xffffffffu, pm0, o);
            float os0 = __shfl_xor_sync(0xffffffffu, ps0, o);
            float om1 = __shfl_xor_sync(0xffffffffu, pm1, o);
            float os1 = __shfl_xor_sync(0xffffffffu, ps1, o);
            osm_merge(pm0, ps0, om0, os0);
            osm_merge(pm1, ps1, om1, os1);
        }
        const float m0 = __shfl_sync(0xffffffffu, pm0, 0);
        const float sum0 = __shfl_sync(0xffffffffu, ps0, 0);
        const float m1 = __shfl_sync(0xffffffffu, pm1, 0);
        const float sum1 = __shfl_sync(0xffffffffu, ps1, 0);
        const float inv0 = 1.f / sum0, inv1 = 1.f / sum1;

        float carry0 = 0.f, carry1 = 0.f;
        float mm0 = -3.4e38f, mm1 = -3.4e38f;
        const int nch = (L1 + 31) >> 5;
        for (int c = 0; c < nch; c++) {
            int s = c * 32 + lane;
            bool v0 = (s < L0), v1 = (s < L1);
            float x0 = v0 ? row0[s] : 0.f;
            float x1 = v1 ? row1[s] : 0.f;
            float e0 = v0 ? fexp(x0 - m0) * inv0 : 0.f;
            float e1 = v1 ? fexp(x1 - m1) * inv1 : 0.f;
            float s0v = e0, s1v = e1;
#pragma unroll
            for (int o = 1; o < 32; o <<= 1) {
                float n0 = __shfl_up_sync(0xffffffffu, s0v, o);
                float n1 = __shfl_up_sync(0xffffffffu, s1v, o);
                if (lane >= o) { s0v += n0; s1v += n1; }
            }
            float cum0 = carry0 + s0v, cum1 = carry1 + s1v;
            carry0 += __shfl_sync(0xffffffffu, s0v, 31);
            carry1 += __shfl_sync(0xffffffffu, s1v, 31);
            if (v0) {
                float pos = (float)(tg0 - s);
                float ds = fsqrt(fmaxf((1.f - cum0) * pos, 0.f));
                float eff = fminf(fmaxf(fexp(ds * gamma), 1e-5f), 1e5f);
                float y = x0 * eff;
                row0[s] = y;
                mm0 = fmaxf(mm0, y);
            }
            if (v1) {
                float pos = (float)(tg1 - s);
                float ds = fsqrt(fmaxf((1.f - cum1) * pos, 0.f));
                float eff = fminf(fmaxf(fexp(ds * gamma), 1e-5f), 1e5f);
                float y = x1 * eff;
                row1[s] = y;
                mm1 = fmaxf(mm1, y);
            }
        }
        mm0 = wredmax(mm0); mm1 = wredmax(mm1);

        float s20 = 0.f, s21 = 0.f;
        for (int s = lane; s < L1; s += 32) {
            if (s < L0) {
                float e = fexp(row0[s] - mm0);
                row0[s] = e;
                s20 += e;
            }
            float e = fexp(row1[s] - mm1);
            row1[s] = e;
            s21 += e;
        }
        s20 = wredsum(s20); s21 = wredsum(s21);
        if (lane == 0) {
            row0[1024] = (tg0 == 0) ? 0.f : 1.f / s20;   // inv2 in row padding
            row1[1024] = (tg1 == 0) ? 0.f : 1.f / s21;
        }
    }
    __syncthreads();

    // ==================== PV phase (mma.sync, 16 warps) ====================
    const int wm = w >> 3;          // 0..1 (m16 tile)
    const int wn = w & 7;           // 0..7 (8-d column group)
    float am[4], acv[4];
#pragma unroll
    for (int q = 0; q < 4; q++) { am[q] = 0.f; acv[q] = 0.f; }

    const unsigned short* Vmh = g_vmh + (size_t)bh * DK_ * T_;
    const unsigned short* Vml = g_vml + (size_t)bh * DK_ * T_;
    const unsigned short* Vch = g_vch + (size_t)bh * DK_ * T_;
    const unsigned short* Vcl = g_vcl + (size_t)bh * DK_ * T_;

    const uint32_t x2row = (uint32_t)(wn * 8 + (lane & 7));
    const uint32_t x2half = (uint32_t)((lane >> 3) & 1);

    for (int st = 0; st < NT; st++) {
        const int S0 = st * 128;
        __syncthreads();
        // convert P chunk -> bf16 hi/lo + P^2 hi/lo (normalize + causal-zero fused)
        {
            int idx = tid;
            uint32_t r = (uint32_t)(idx >> 4), gg = (uint32_t)(idx & 15);
            const float* prow = sc + (size_t)r * SC_STRIDE;
            const float inv2 = prow[1024];
            const int tg = t0 + (int)r;
            unsigned short ph[8], pl[8], qh2[8], ql2[8];
#pragma unroll
            for (int j = 0; j < 8; j++) {
                int s = S0 + (int)gg * 8 + j;
                float p = (s <= tg) ? prow[s] * inv2 : 0.f;
                bf16split(p, ph[j], pl[j]);
                bf16split(p * p, qh2[j], ql2[j]);
            }
            uint32_t so = swz128(r, gg);
            *(uint4*)(stg + so) = *(uint4*)ph;
            *(uint4*)(stg + 8192 + so) = *(uint4*)pl;
            *(uint4*)(stg + 16384 + so) = *(uint4*)qh2;
            *(uint4*)(stg + 24576 + so) = *(uint4*)ql2;
        }
        // load V tiles [64][128] x4 arrays (4096 items, 8 iters)
#pragma unroll
        for (int it = 0; it < 8; it++) {
            int idx = it * 512 + tid;
            int arr = idx >> 10;
            uint32_t r = (uint32_t)((idx >> 4) & 63), gg = (uint32_t)(idx & 15);
            const unsigned short* src =
                (arr == 0 ? Vmh : arr == 1 ? Vml : arr == 2 ? Vch : Vcl) + (size_t)r * T_ + S0 + gg * 8;
            *(uint4*)(stg + 32768 + arr * 16384 + swz128(r, gg)) = *(const uint4*)src;
        }
        __syncthreads();

#pragma unroll
        for (int ks = 0; ks < 8; ks++) {
            uint32_t cbA = (uint32_t)(ks * 2 + a_c);
            uint32_t cbB2 = (uint32_t)(ks * 2 + x2half);
            uint32_t ap[4], al2[4], a2p[4], a2l[4];
            uint32_t ra = (uint32_t)(wm * 16 + a_r);
            ldsm_x4(ap,  aPh  + swz128(ra, cbA));
            ldsm_x4(al2, aPl  + swz128(ra, cbA));
            ldsm_x4(a2p, aP2h + swz128(ra, cbA));
            ldsm_x4(a2l, aP2l + swz128(ra, cbA));

            uint32_t bmh[2], bml[2], bch[2], bcl[2];
            uint32_t boff = swz128(x2row, cbB2);
            ldsm_x2(bmh, aVmh + boff);
            ldsm_x2(bml, aVml + boff);
            ldsm_x2(bch, aVch + boff);
            ldsm_x2(bcl, aVcl + boff);

            mma16816(am, ap, bmh);
            mma16816(am, ap, bml);
            mma16816(am, al2, bmh);
            mma16816(acv, a2p, bch);
            mma16816(acv, a2p, bcl);
            mma16816(acv, a2l, bch);
        }
    }

    // write outputs directly as bf16 hi/lo (fused split_c)
    {
        int col = h * 64 + wn * 8 + 2 * t2;
#pragma unroll
        for (int half = 0; half < 2; half++) {
            int trow = t0 + wm * 16 + g8 + half * 8;
            size_t o = (size_t)(b * 1024 + trow) * 512 + col;
            unsigned short mh0, ml0, mh1, ml1, ch0, cl0, ch1, cl1;
            bf16split(am[half * 2],      mh0, ml0);
            bf16split(am[half * 2 + 1],  mh1, ml1);
            bf16split(acv[half * 2],     ch0, cl0);
            bf16split(acv[half * 2 + 1], ch1, cl1);
            *(ushort2*)((unsigned short*)&g_chi[0][0] + o) = make_ushort2(mh0, mh1);
            *(ushort2*)((unsigned short*)&g_clo[0][0] + o) = make_ushort2(ml0, ml1);
            *(ushort2*)((unsigned short*)&g_chi[1][0] + o) = make_ushort2(ch0, ch1);
            *(ushort2*)((unsigned short*)&g_clo[1][0] + o) = make_ushort2(cl0, cl1);
        }
    }
}

// ---------------- launch ----------------
extern "C" void kernel_launch(void* const* d_in, const int* in_sizes, int n_in,
                              void* d_out, int out_size)
{
    const float* q_mean  = (const float*)d_in[0];
    const float* q_cov   = (const float*)d_in[1];
    const float* k_mean  = (const float*)d_in[2];
    const float* k_cov   = (const float*)d_in[3];
    const float* v_mean  = (const float*)d_in[4];
    const float* v_cov   = (const float*)d_in[5];
    const float* Wk_mean = (const float*)d_in[6];
    const float* bk_mean = (const float*)d_in[7];
    const float* Wk_cov  = (const float*)d_in[8];
    const float* bk_cov  = (const float*)d_in[9];
    const float* Wv_mean = (const float*)d_in[10];
    const float* bv_mean = (const float*)d_in[11];
    const float* Wv_cov  = (const float*)d_in[12];
    const float* bv_cov  = (const float*)d_in[13];
    const float* Wo_mean = (const float*)d_in[14];
    const float* bo_mean = (const float*)d_in[15];
    const float* Wo_cov  = (const float*)d_in[16];
    const float* bo_cov  = (const float*)d_in[17];
    const float* gammas  = (const float*)d_in[18];
    float* out = (float*)d_out;

    // launch 0: projection GEMMs (fp32 inputs, split fused into staging)
    cudaFuncSetAttribute(gemm_mma, cudaFuncAttributeMaxDynamicSharedMemorySize, GEMM_SMEM);
    GemmArgs gp;
    gp.bias[0] = bk_mean; gp.bias[1] = bk_cov; gp.bias[2] = bv_mean;
    gp.bias[3] = bv_cov;  gp.bias[4] = bo_mean; gp.bias[5] = bo_cov;
    gp.Af[0] = q_mean; gp.Af[1] = q_cov; gp.Af[2] = k_mean;
    gp.Af[3] = k_cov;  gp.Af[4] = v_mean; gp.Af[5] = v_cov;
    gp.Wf[0] = Wk_mean; gp.Wf[1] = Wk_cov; gp.Wf[2] = Wv_mean;
    gp.Wf[3] = Wv_cov;  gp.Wf[4] = Wo_mean; gp.Wf[5] = Wo_cov;
    gp.out = nullptr; gp.is_out = 0;
    gemm_mma<<<dim3(4, 64, 6), 256, GEMM_SMEM>>>(gp);

    // launch 1: pack Q/K/V (+rowsums)
    pack_all<<<8192, 256>>>();

    // launch 2: fused attention (1D grid, globally heavy-first)
    cudaFuncSetAttribute(attn_kernel, cudaFuncAttributeMaxDynamicSharedMemorySize, ATTN_SMEM);
    attn_kernel<<<2048, 512, ATTN_SMEM>>>(gammas);

    // launch 3: output GEMMs
    GemmArgs go = gp;
    go.out = out; go.is_out = 1;
    gemm_mma<<<dim3(4, 64, 2), 256, GEMM_SMEM>>>(go);
}